// round 2
// baseline (speedup 1.0000x reference)
#include <cuda_runtime.h>
#include <math.h>

// Problem dims (fixed by the dataset)
#define BSZ 4
#define LSZ 2048
#define DSZ 512
#define MROWS (BSZ * LSZ)   // 8192

// Scan chunking
#define NC 64               // chunks along L
#define LC (LSZ / NC)       // 32 steps per chunk

// ---------------------------------------------------------------------------
// Scratch (static device globals; no runtime allocation allowed)
// ---------------------------------------------------------------------------
__device__ float  g_angle[BSZ * LSZ * DSZ];   // GEMM output (pre-activation angles)
__device__ float2 g_P[BSZ * NC * DSZ];        // per-chunk multiplier product
__device__ float2 g_E[BSZ * NC * DSZ];        // per-chunk local end state

// ---------------------------------------------------------------------------
// Kernel 1: angle = x @ W^T + b   (fp32 SGEMM, 128x128x8 tiles, 8x8 per thread)
// A: [M,K] row-major, W: [N,K] row-major (so C = A * W^T), C -> g_angle
// ---------------------------------------------------------------------------
#define BM 128
#define BN 128
#define BKK 8
#define TM 8
#define TN 8

__global__ __launch_bounds__(256) void gemm_kernel(
    const float* __restrict__ A, const float* __restrict__ W,
    const float* __restrict__ bias)
{
    const int K = DSZ;
    const int N = DSZ;

    __shared__ float As[BKK][BM];
    __shared__ float Bs[BKK][BN];

    const int tid = threadIdx.x;
    const int bm = blockIdx.y * BM;
    const int bn = blockIdx.x * BN;

    const int lr  = tid >> 1;          // 0..127 : row within tile
    const int lc4 = (tid & 1) * 4;     // 0 or 4 : k offset

    const int tr = (tid >> 4) * TM;    // 0..120
    const int tc = (tid & 15) * TN;    // 0..120

    float acc[TM][TN];
#pragma unroll
    for (int i = 0; i < TM; i++)
#pragma unroll
        for (int j = 0; j < TN; j++) acc[i][j] = 0.f;

    const float* Arow = A + (size_t)(bm + lr) * K;
    const float* Wrow = W + (size_t)(bn + lr) * K;

    for (int k0 = 0; k0 < K; k0 += BKK) {
        float4 a4 = *(const float4*)(Arow + k0 + lc4);
        float4 b4 = *(const float4*)(Wrow + k0 + lc4);
        As[lc4 + 0][lr] = a4.x; As[lc4 + 1][lr] = a4.y;
        As[lc4 + 2][lr] = a4.z; As[lc4 + 3][lr] = a4.w;
        Bs[lc4 + 0][lr] = b4.x; Bs[lc4 + 1][lr] = b4.y;
        Bs[lc4 + 2][lr] = b4.z; Bs[lc4 + 3][lr] = b4.w;
        __syncthreads();

#pragma unroll
        for (int kk = 0; kk < BKK; kk++) {
            float rm[TM], rn[TN];
#pragma unroll
            for (int i = 0; i < TM; i++) rm[i] = As[kk][tr + i];
#pragma unroll
            for (int j = 0; j < TN; j++) rn[j] = Bs[kk][tc + j];
#pragma unroll
            for (int i = 0; i < TM; i++)
#pragma unroll
                for (int j = 0; j < TN; j++)
                    acc[i][j] = fmaf(rm[i], rn[j], acc[i][j]);
        }
        __syncthreads();
    }

    float bz[TN];
#pragma unroll
    for (int j = 0; j < TN; j++) bz[j] = bias[bn + tc + j];

#pragma unroll
    for (int i = 0; i < TM; i++) {
        float* crow = g_angle + (size_t)(bm + tr + i) * N + bn + tc;
#pragma unroll
        for (int j = 0; j < TN; j += 4) {
            float4 o;
            o.x = acc[i][j + 0] + bz[j + 0];
            o.y = acc[i][j + 1] + bz[j + 1];
            o.z = acc[i][j + 2] + bz[j + 2];
            o.w = acc[i][j + 3] + bz[j + 3];
            *(float4*)(crow + j) = o;
        }
    }
}

// ---------------------------------------------------------------------------
// Complex linear scan:  g[t] = c[t]*g[t-1] + x[t]
//   c[0]   = 1          (masked first step), plus g[0] += exp(ln_phazor[0])*last_conv
//   c[t>0] = e * (cos(angle*scale) + i sin(angle*scale)),  e = exp(-0.001)
// Chunked into NC chunks of LC steps; phase1 emits per-chunk (P, E); phase2
// folds carries, recomputes the chunk scan, and applies LayerNorm in place
// (block = all of D for one (b, chunk)), writing y directly.
// ---------------------------------------------------------------------------
#define EDECAY 0.999000499833375f   // expf(-0.001f)

__global__ __launch_bounds__(512) void scan_phase1(
    const float* __restrict__ x, const float* __restrict__ scale,
    const float* __restrict__ lre, const float* __restrict__ lim)
{
    const int b = blockIdx.x / NC;
    const int c = blockIdx.x % NC;
    const int d = threadIdx.x;

    const float sc = scale[d];
    const size_t base = ((size_t)b * LSZ + (size_t)c * LC) * DSZ + d;
    const float* ap = g_angle + base;
    const float* xp = x + base;

    float gr = 0.f, gi = 0.f, Pr = 1.f, Pi = 0.f;
    int tt = 0;
    if (c == 0) {
        float a0 = ap[0], x0 = xp[0];
        float s0, c0;
        __sincosf(a0 * sc, &s0, &c0);
        const float lr_ = lre[d], li_ = lim[d];
        gr = x0 + EDECAY * (c0 * lr_ - s0 * li_);
        gi = EDECAY * (c0 * li_ + s0 * lr_);
        tt = 1;   // c[0] = 1, so P unchanged
    }
    for (; tt < LC; tt++) {
        float a  = ap[(size_t)tt * DSZ];
        float xv = xp[(size_t)tt * DSZ];
        float s, co;
        __sincosf(a * sc, &s, &co);
        const float cr = EDECAY * co, ci = EDECAY * s;
        float ngr = fmaf(cr, gr, fmaf(-ci, gi, xv));
        float ngi = fmaf(cr, gi, ci * gr);
        gr = ngr; gi = ngi;
        float nPr = fmaf(cr, Pr, -ci * Pi);
        float nPi = fmaf(cr, Pi,  ci * Pr);
        Pr = nPr; Pi = nPi;
    }
    const int idx = (b * NC + c) * DSZ + d;
    g_E[idx] = make_float2(gr, gi);
    g_P[idx] = make_float2(Pr, Pi);
}

// Phase 2 with fused LayerNorm. One block per (b, chunk), 512 threads = D.
__global__ __launch_bounds__(512) void scan_phase2_ln(
    const float* __restrict__ x, const float* __restrict__ scale,
    const float* __restrict__ lre, const float* __restrict__ lim,
    const float* __restrict__ gamma, const float* __restrict__ beta,
    float* __restrict__ y)
{
    const int b = blockIdx.x / NC;
    const int c = blockIdx.x % NC;
    const int d = threadIdx.x;
    const int w = d >> 5, l = d & 31;

    __shared__ float sh_s[16], sh_ss[16];

    const float sc = scale[d];
    const float gm = gamma[d];
    const float bt = beta[d];

    // fold carries from preceding chunks: s <- P_j * s + E_j, j ascending
    float gr = 0.f, gi = 0.f;
    for (int j = 0; j < c; j++) {
        const int idx = (b * NC + j) * DSZ + d;
        const float2 P = g_P[idx];
        const float2 E = g_E[idx];
        float ngr = fmaf(P.x, gr, fmaf(-P.y, gi, E.x));
        float ngi = fmaf(P.x, gi, fmaf( P.y, gr, E.y));
        gr = ngr; gi = ngi;
    }

    const size_t base = ((size_t)b * LSZ + (size_t)c * LC) * DSZ + d;
    const float* ap = g_angle + base;
    const float* xp = x + base;
    float* yp = y + base;

    for (int tt = 0; tt < LC; tt++) {
        float a  = ap[(size_t)tt * DSZ];
        float xv = xp[(size_t)tt * DSZ];
        float s, co;
        __sincosf(a * sc, &s, &co);
        if (c == 0 && tt == 0) {
            // masked first step: c[0]=1, plus cross-term seed
            const float lr_ = lre[d], li_ = lim[d];
            gr = xv + EDECAY * (co * lr_ - s * li_);
            gi = EDECAY * (co * li_ + s * lr_);
        } else {
            const float cr = EDECAY * co, ci = EDECAY * s;
            float ngr = fmaf(cr, gr, fmaf(-ci, gi, xv));
            float ngi = fmaf(cr, gi, ci * gr);
            gr = ngr; gi = ngi;
        }

        // ---- fused LayerNorm over d for this timestep ----
        float sm  = gr;
        float ssq = gr * gr;
#pragma unroll
        for (int o = 16; o > 0; o >>= 1) {
            sm  += __shfl_xor_sync(0xffffffffu, sm,  o);
            ssq += __shfl_xor_sync(0xffffffffu, ssq, o);
        }
        if (l == 0) { sh_s[w] = sm; sh_ss[w] = ssq; }
        __syncthreads();
        float tot_s = 0.f, tot_ss = 0.f;
#pragma unroll
        for (int k = 0; k < 16; k++) { tot_s += sh_s[k]; tot_ss += sh_ss[k]; }

        const float mu   = tot_s * (1.0f / DSZ);
        const float var  = tot_ss * (1.0f / DSZ) - mu * mu;
        const float rstd = rsqrtf(var + 1e-5f);
        yp[(size_t)tt * DSZ] = (gr - mu) * rstd * gm + bt;
        __syncthreads();   // protect sh_* reuse next iteration
    }
}

// ---------------------------------------------------------------------------
// Launch
// ---------------------------------------------------------------------------
extern "C" void kernel_launch(void* const* d_in, const int* in_sizes, int n_in,
                              void* d_out, int out_size)
{
    const float* x     = (const float*)d_in[0];
    const float* fc_w  = (const float*)d_in[1];
    const float* fc_b  = (const float*)d_in[2];
    const float* scale = (const float*)d_in[3];
    const float* lre   = (const float*)d_in[4];
    const float* lim   = (const float*)d_in[5];
    const float* gamma = (const float*)d_in[6];
    const float* beta  = (const float*)d_in[7];
    float* y = (float*)d_out;

    dim3 ggrid(DSZ / BN, MROWS / BM);           // (4, 64)
    gemm_kernel<<<ggrid, 256>>>(x, fc_w, fc_b);

    scan_phase1<<<BSZ * NC, DSZ>>>(x, scale, lre, lim);
    scan_phase2_ln<<<BSZ * NC, DSZ>>>(x, scale, lre, lim, gamma, beta, y);
}

// round 4
// speedup vs baseline: 1.2017x; 1.2017x over previous
#include <cuda_runtime.h>
#include <math.h>
#include <stdint.h>

// Problem dims (fixed by the dataset)
#define BSZ 4
#define LSZ 2048
#define DSZ 512
#define MROWS (BSZ * LSZ)   // 8192

// Scan chunking
#define NC 64               // chunks along L
#define LC (LSZ / NC)       // 32 steps per chunk

// GEMM tiling
#define BM 128
#define BN 128
#define BK 32
#define NCHUNK (DSZ / BK)   // 16

// ---------------------------------------------------------------------------
// Scratch (static device globals; no runtime allocation allowed)
// ---------------------------------------------------------------------------
__device__ float  g_angle[MROWS * DSZ];
__device__ float2 g_P[BSZ * NC * DSZ];
__device__ float2 g_E[BSZ * NC * DSZ];

// ---------------------------------------------------------------------------
// tf32 helpers (all baseline sm_80+ PTX; no arch-suffix features)
// ---------------------------------------------------------------------------
__device__ __forceinline__ uint32_t tf32_rna(float v) {
    uint32_t u;
    asm("cvt.rna.tf32.f32 %0, %1;" : "=r"(u) : "f"(v));
    return u;
}

// D += A * B  (m16n8k8, A row-major 16x8, B col-major 8x8, fp32 accum)
__device__ __forceinline__ void mma8(float* d, const uint32_t* a, const uint32_t* b) {
    asm volatile(
        "mma.sync.aligned.m16n8k8.row.col.f32.tf32.tf32.f32 "
        "{%0,%1,%2,%3}, {%4,%5,%6,%7}, {%8,%9}, {%0,%1,%2,%3};"
        : "+f"(d[0]), "+f"(d[1]), "+f"(d[2]), "+f"(d[3])
        : "r"(a[0]), "r"(a[1]), "r"(a[2]), "r"(a[3]), "r"(b[0]), "r"(b[1]));
}

// ---------------------------------------------------------------------------
// GEMM: angle = x @ W^T + b, split-tf32 (hi*hi + hi*lo + lo*hi), mma.sync.
//   A: [MROWS, DSZ] row-major, W: [DSZ, DSZ] row-major (B of the MMA = W^T).
// SMEM (dynamic, 64 KB): Ahi[128*32] Alo Whi Wlo, XOR-swizzled columns.
// 256 threads = 8 warps (4m x 2n), warp tile 32x64, C frag 2x8x4 per thread.
// ---------------------------------------------------------------------------
#define SMEM_FLOATS (4 * BM * BK)
#define GEMM_SMEM   (SMEM_FLOATS * 4)

__global__ __launch_bounds__(256, 1) void gemm_mma(
    const float* __restrict__ A, const float* __restrict__ W,
    const float* __restrict__ bias)
{
    extern __shared__ uint32_t sm[];
    uint32_t* Ahi = sm;
    uint32_t* Alo = sm + BM * BK;
    uint32_t* Whi = sm + 2 * BM * BK;
    uint32_t* Wlo = sm + 3 * BM * BK;

    const int tid  = threadIdx.x;
    const int wid  = tid >> 5;
    const int lane = tid & 31;
    const int g    = lane >> 2;     // group 0..7
    const int tg   = lane & 3;      // thread-in-group 0..3
    const int bm   = blockIdx.y * BM;
    const int bn   = blockIdx.x * BN;
    const int m0w  = (wid >> 1) * 32;   // warp m offset
    const int n0w  = (wid & 1) * 64;    // warp n offset

    // staging assignment: row = tid>>1 (0..127), 16-float half = (tid&1)*16
    const int srow = tid >> 1;
    const int skh  = (tid & 1) * 16;
    const int sxo  = (srow & 7) << 2;  // column XOR swizzle
    const float* Ag = A + (size_t)(bm + srow) * DSZ + skh;
    const float* Wg = W + (size_t)(bn + srow) * DSZ + skh;

    float4 pa[4], pw[4];
    auto ldg_chunk = [&](int c) {
        const float* ap = Ag + c * BK;
        const float* wp = Wg + c * BK;
#pragma unroll
        for (int j = 0; j < 4; j++) {
            pa[j] = *(const float4*)(ap + 4 * j);
            pw[j] = *(const float4*)(wp + 4 * j);
        }
    };
    auto sts_chunk = [&]() {
#pragma unroll
        for (int j = 0; j < 4; j++) {
            const int idx = srow * BK + ((skh + 4 * j) ^ sxo);
            uint4 h, l;
            h.x = tf32_rna(pa[j].x); l.x = tf32_rna(pa[j].x - __uint_as_float(h.x));
            h.y = tf32_rna(pa[j].y); l.y = tf32_rna(pa[j].y - __uint_as_float(h.y));
            h.z = tf32_rna(pa[j].z); l.z = tf32_rna(pa[j].z - __uint_as_float(h.z));
            h.w = tf32_rna(pa[j].w); l.w = tf32_rna(pa[j].w - __uint_as_float(h.w));
            *(uint4*)(Ahi + idx) = h;
            *(uint4*)(Alo + idx) = l;
            h.x = tf32_rna(pw[j].x); l.x = tf32_rna(pw[j].x - __uint_as_float(h.x));
            h.y = tf32_rna(pw[j].y); l.y = tf32_rna(pw[j].y - __uint_as_float(h.y));
            h.z = tf32_rna(pw[j].z); l.z = tf32_rna(pw[j].z - __uint_as_float(h.z));
            h.w = tf32_rna(pw[j].w); l.w = tf32_rna(pw[j].w - __uint_as_float(h.w));
            *(uint4*)(Whi + idx) = h;
            *(uint4*)(Wlo + idx) = l;
        }
    };

    float C[2][8][4];
#pragma unroll
    for (int mt = 0; mt < 2; mt++)
#pragma unroll
        for (int nt = 0; nt < 8; nt++)
#pragma unroll
            for (int j = 0; j < 4; j++) C[mt][nt][j] = 0.f;

    const int fxo = g << 2;  // fragment-load XOR (rows differ by 8 -> same &7)

    ldg_chunk(0);
    for (int c = 0; c < NCHUNK; c++) {
        __syncthreads();          // smem free (prev chunk's mma done)
        sts_chunk();
        __syncthreads();
        if (c + 1 < NCHUNK) ldg_chunk(c + 1);

#pragma unroll
        for (int k0 = 0; k0 < BK; k0 += 8) {
            const int c0 = (k0 + tg) ^ fxo;
            const int c1 = (k0 + tg + 4) ^ fxo;

            uint32_t ah[2][4], al[2][4];
#pragma unroll
            for (int mt = 0; mt < 2; mt++) {
                const int r0 = (m0w + mt * 16 + g) * BK;
                const int r1 = r0 + 8 * BK;
                ah[mt][0] = Ahi[r0 + c0]; ah[mt][1] = Ahi[r1 + c0];
                ah[mt][2] = Ahi[r0 + c1]; ah[mt][3] = Ahi[r1 + c1];
                al[mt][0] = Alo[r0 + c0]; al[mt][1] = Alo[r1 + c0];
                al[mt][2] = Alo[r0 + c1]; al[mt][3] = Alo[r1 + c1];
            }
#pragma unroll
            for (int nt = 0; nt < 8; nt++) {
                const int nr = (n0w + nt * 8 + g) * BK;
                uint32_t bh[2] = { Whi[nr + c0], Whi[nr + c1] };
                uint32_t bl[2] = { Wlo[nr + c0], Wlo[nr + c1] };
#pragma unroll
                for (int mt = 0; mt < 2; mt++) {
                    mma8(C[mt][nt], ah[mt], bh);
                    mma8(C[mt][nt], ah[mt], bl);
                    mma8(C[mt][nt], al[mt], bh);
                }
            }
        }
    }

    // epilogue: C + bias -> g_angle (float2 stores)
#pragma unroll
    for (int nt = 0; nt < 8; nt++) {
        const int col = bn + n0w + nt * 8 + 2 * tg;
        const float bz0 = bias[col], bz1 = bias[col + 1];
#pragma unroll
        for (int mt = 0; mt < 2; mt++) {
            const int row = bm + m0w + mt * 16 + g;
            float2 v0 = make_float2(C[mt][nt][0] + bz0, C[mt][nt][1] + bz1);
            float2 v1 = make_float2(C[mt][nt][2] + bz0, C[mt][nt][3] + bz1);
            *(float2*)(g_angle + (size_t)row * DSZ + col) = v0;
            *(float2*)(g_angle + (size_t)(row + 8) * DSZ + col) = v1;
        }
    }
}

// ---------------------------------------------------------------------------
// Complex linear scan:  g[t] = c[t]*g[t-1] + x[t]
// ---------------------------------------------------------------------------
#define EDECAY 0.999000499833375f   // expf(-0.001f)

__global__ __launch_bounds__(512) void scan_phase1(
    const float* __restrict__ x, const float* __restrict__ scale,
    const float* __restrict__ lre, const float* __restrict__ lim)
{
    const int b = blockIdx.x / NC;
    const int c = blockIdx.x % NC;
    const int d = threadIdx.x;

    const float sc = scale[d];
    const size_t base = ((size_t)b * LSZ + (size_t)c * LC) * DSZ + d;
    const float* ap = g_angle + base;
    const float* xp = x + base;

    float gr = 0.f, gi = 0.f, Pr = 1.f, Pi = 0.f;
    int tt = 0;
    if (c == 0) {
        float a0 = ap[0], x0 = xp[0];
        float s0, c0;
        __sincosf(a0 * sc, &s0, &c0);
        const float lr_ = lre[d], li_ = lim[d];
        gr = x0 + EDECAY * (c0 * lr_ - s0 * li_);
        gi = EDECAY * (c0 * li_ + s0 * lr_);
        tt = 1;
    }
    for (; tt < LC; tt++) {
        float a  = ap[(size_t)tt * DSZ];
        float xv = xp[(size_t)tt * DSZ];
        float s, co;
        __sincosf(a * sc, &s, &co);
        const float cr = EDECAY * co, ci = EDECAY * s;
        float ngr = fmaf(cr, gr, fmaf(-ci, gi, xv));
        float ngi = fmaf(cr, gi, ci * gr);
        gr = ngr; gi = ngi;
        float nPr = fmaf(cr, Pr, -ci * Pi);
        float nPi = fmaf(cr, Pi,  ci * Pr);
        Pr = nPr; Pi = nPi;
    }
    const int idx = (b * NC + c) * DSZ + d;
    g_E[idx] = make_float2(gr, gi);
    g_P[idx] = make_float2(Pr, Pi);
}

__global__ __launch_bounds__(512) void scan_phase2_ln(
    const float* __restrict__ x, const float* __restrict__ scale,
    const float* __restrict__ lre, const float* __restrict__ lim,
    const float* __restrict__ gamma, const float* __restrict__ beta,
    float* __restrict__ y)
{
    const int b = blockIdx.x / NC;
    const int c = blockIdx.x % NC;
    const int d = threadIdx.x;
    const int w = d >> 5, l = d & 31;

    __shared__ float sh_s[16], sh_ss[16];

    const float sc = scale[d];
    const float gm = gamma[d];
    const float bt = beta[d];

    float gr = 0.f, gi = 0.f;
    for (int j = 0; j < c; j++) {
        const int idx = (b * NC + j) * DSZ + d;
        const float2 P = g_P[idx];
        const float2 E = g_E[idx];
        float ngr = fmaf(P.x, gr, fmaf(-P.y, gi, E.x));
        float ngi = fmaf(P.x, gi, fmaf( P.y, gr, E.y));
        gr = ngr; gi = ngi;
    }

    const size_t base = ((size_t)b * LSZ + (size_t)c * LC) * DSZ + d;
    const float* ap = g_angle + base;
    const float* xp = x + base;
    float* yp = y + base;

    for (int tt = 0; tt < LC; tt++) {
        float a  = ap[(size_t)tt * DSZ];
        float xv = xp[(size_t)tt * DSZ];
        float s, co;
        __sincosf(a * sc, &s, &co);
        if (c == 0 && tt == 0) {
            const float lr_ = lre[d], li_ = lim[d];
            gr = xv + EDECAY * (co * lr_ - s * li_);
            gi = EDECAY * (co * li_ + s * lr_);
        } else {
            const float cr = EDECAY * co, ci = EDECAY * s;
            float ngr = fmaf(cr, gr, fmaf(-ci, gi, xv));
            float ngi = fmaf(cr, gi, ci * gr);
            gr = ngr; gi = ngi;
        }

        float sm  = gr;
        float ssq = gr * gr;
#pragma unroll
        for (int o = 16; o > 0; o >>= 1) {
            sm  += __shfl_xor_sync(0xffffffffu, sm,  o);
            ssq += __shfl_xor_sync(0xffffffffu, ssq, o);
        }
        if (l == 0) { sh_s[w] = sm; sh_ss[w] = ssq; }
        __syncthreads();
        float tot_s = 0.f, tot_ss = 0.f;
#pragma unroll
        for (int kk = 0; kk < 16; kk++) { tot_s += sh_s[kk]; tot_ss += sh_ss[kk]; }

        const float mu   = tot_s * (1.0f / DSZ);
        const float var  = tot_ss * (1.0f / DSZ) - mu * mu;
        const float rstd = rsqrtf(var + 1e-5f);
        yp[(size_t)tt * DSZ] = (gr - mu) * rstd * gm + bt;
        __syncthreads();
    }
}

// ---------------------------------------------------------------------------
// Launch
// ---------------------------------------------------------------------------
extern "C" void kernel_launch(void* const* d_in, const int* in_sizes, int n_in,
                              void* d_out, int out_size)
{
    const float* x     = (const float*)d_in[0];
    const float* fc_w  = (const float*)d_in[1];
    const float* fc_b  = (const float*)d_in[2];
    const float* scale = (const float*)d_in[3];
    const float* lre   = (const float*)d_in[4];
    const float* lim   = (const float*)d_in[5];
    const float* gamma = (const float*)d_in[6];
    const float* beta  = (const float*)d_in[7];
    float* y = (float*)d_out;

    static bool attr_set = false;
    if (!attr_set) {
        cudaFuncSetAttribute(gemm_mma, cudaFuncAttributeMaxDynamicSharedMemorySize,
                             GEMM_SMEM);
        attr_set = true;
    }

    dim3 ggrid(DSZ / BN, MROWS / BM);   // (4, 64) = 256 CTAs
    gemm_mma<<<ggrid, 256, GEMM_SMEM>>>(x, fc_w, fc_b);

    scan_phase1<<<BSZ * NC, DSZ>>>(x, scale, lre, lim);
    scan_phase2_ln<<<BSZ * NC, DSZ>>>(x, scale, lre, lim, gamma, beta, y);
}

// round 5
// speedup vs baseline: 1.6352x; 1.3608x over previous
#include <cuda_runtime.h>
#include <cuda_fp16.h>
#include <math.h>
#include <stdint.h>

// Problem dims (fixed by the dataset)
#define BSZ 4
#define LSZ 2048
#define DSZ 512
#define MROWS (BSZ * LSZ)   // 8192

// Scan chunking
#define NC 64               // chunks along L
#define LC (LSZ / NC)       // 32 steps per chunk

// GEMM tiling
#define BM 128
#define BN 128
#define BK 32
#define NCHUNK (DSZ / BK)   // 16

// smem layout: half2 words (4B). Row = 16 words of data padded to 20 (80B)
// -> 20*r mod 32 spans 8 distinct banks: fragment LDS conflict-free.
#define ROWW 20
#define MAT_WORDS (BM * ROWW)          // 2560 words = 10KB per matrix
#define STAGE_WORDS (4 * MAT_WORDS)    // Ahi|Alo|Whi|Wlo = 40KB
#define GEMM_SMEM (2 * STAGE_WORDS * 4)  // double buffered: 80KB

// ---------------------------------------------------------------------------
// Scratch (static device globals; no runtime allocation allowed)
// ---------------------------------------------------------------------------
__device__ float  g_angle[MROWS * DSZ];
__device__ float2 g_P[BSZ * NC * DSZ];
__device__ float2 g_E[BSZ * NC * DSZ];

// ---------------------------------------------------------------------------
// fp16 split helpers (baseline sm_80+ PTX only)
// ---------------------------------------------------------------------------
__device__ __forceinline__ void split2(float x, float y, uint32_t& hi, uint32_t& lo) {
    __half2 h = __floats2half2_rn(x, y);
    float2 hf = __half22float2(h);
    __half2 l = __floats2half2_rn(x - hf.x, y - hf.y);
    hi = *reinterpret_cast<uint32_t*>(&h);
    lo = *reinterpret_cast<uint32_t*>(&l);
}

// D += A * B  (m16n8k16 fp16, fp32 accum; A row-major 16x16, B col-major 16x8)
__device__ __forceinline__ void mma16(float* d, const uint32_t* a, const uint32_t* b) {
    asm volatile(
        "mma.sync.aligned.m16n8k16.row.col.f32.f16.f16.f32 "
        "{%0,%1,%2,%3}, {%4,%5,%6,%7}, {%8,%9}, {%0,%1,%2,%3};"
        : "+f"(d[0]), "+f"(d[1]), "+f"(d[2]), "+f"(d[3])
        : "r"(a[0]), "r"(a[1]), "r"(a[2]), "r"(a[3]), "r"(b[0]), "r"(b[1]));
}

// ---------------------------------------------------------------------------
// GEMM: angle = x @ W^T + b, split-fp16 (hi*hi + hi*lo + lo*hi), mma.sync.
// 256 threads = 8 warps (4m x 2n), warp tile 32x64, C frag [2][8][4].
// Double-buffered smem stage; one __syncthreads per K-chunk.
// ---------------------------------------------------------------------------
__global__ __launch_bounds__(256, 1) void gemm_mma(
    const float* __restrict__ A, const float* __restrict__ W,
    const float* __restrict__ bias)
{
    extern __shared__ uint32_t sm[];

    const int tid  = threadIdx.x;
    const int wid  = tid >> 5;
    const int lane = tid & 31;
    const int g    = lane >> 2;     // group 0..7
    const int tg   = lane & 3;      // thread-in-group 0..3
    const int bm   = blockIdx.y * BM;
    const int bn   = blockIdx.x * BN;
    const int m0w  = (wid >> 1) * 32;   // warp m offset
    const int n0w  = (wid & 1) * 64;    // warp n offset

    // staging: row = tid>>1 (0..127), 16-float half = (tid&1)*16
    const int srow = tid >> 1;
    const int h16  = tid & 1;           // which 16-float half
    const float* Ag = A + (size_t)(bm + srow) * DSZ + h16 * 16;
    const float* Wg = W + (size_t)(bn + srow) * DSZ + h16 * 16;

    float4 pa[4], pw[4];
    auto ldg_chunk = [&](int c) {
        const float* ap = Ag + c * BK;
        const float* wp = Wg + c * BK;
#pragma unroll
        for (int j = 0; j < 4; j++) {
            pa[j] = *(const float4*)(ap + 4 * j);
            pw[j] = *(const float4*)(wp + 4 * j);
        }
    };

    auto sts_chunk = [&](int buf) {
        uint32_t* st = sm + buf * STAGE_WORDS;
        const int base = srow * ROWW + h16 * 8;   // word offset, 4-aligned
        uint4 H0, H1, L0, L1;
        split2(pa[0].x, pa[0].y, H0.x, L0.x);
        split2(pa[0].z, pa[0].w, H0.y, L0.y);
        split2(pa[1].x, pa[1].y, H0.z, L0.z);
        split2(pa[1].z, pa[1].w, H0.w, L0.w);
        split2(pa[2].x, pa[2].y, H1.x, L1.x);
        split2(pa[2].z, pa[2].w, H1.y, L1.y);
        split2(pa[3].x, pa[3].y, H1.z, L1.z);
        split2(pa[3].z, pa[3].w, H1.w, L1.w);
        *(uint4*)(st + base)                 = H0;
        *(uint4*)(st + base + 4)             = H1;
        *(uint4*)(st + MAT_WORDS + base)     = L0;
        *(uint4*)(st + MAT_WORDS + base + 4) = L1;
        split2(pw[0].x, pw[0].y, H0.x, L0.x);
        split2(pw[0].z, pw[0].w, H0.y, L0.y);
        split2(pw[1].x, pw[1].y, H0.z, L0.z);
        split2(pw[1].z, pw[1].w, H0.w, L0.w);
        split2(pw[2].x, pw[2].y, H1.x, L1.x);
        split2(pw[2].z, pw[2].w, H1.y, L1.y);
        split2(pw[3].x, pw[3].y, H1.z, L1.z);
        split2(pw[3].z, pw[3].w, H1.w, L1.w);
        *(uint4*)(st + 2 * MAT_WORDS + base)     = H0;
        *(uint4*)(st + 2 * MAT_WORDS + base + 4) = H1;
        *(uint4*)(st + 3 * MAT_WORDS + base)     = L0;
        *(uint4*)(st + 3 * MAT_WORDS + base + 4) = L1;
    };

    float C[2][8][4];
#pragma unroll
    for (int mt = 0; mt < 2; mt++)
#pragma unroll
        for (int nt = 0; nt < 8; nt++)
#pragma unroll
            for (int j = 0; j < 4; j++) C[mt][nt][j] = 0.f;

    ldg_chunk(0);
    for (int c = 0; c < NCHUNK; c++) {
        const int buf = c & 1;
        sts_chunk(buf);
        __syncthreads();
        if (c + 1 < NCHUNK) ldg_chunk(c + 1);

        const uint32_t* Ahi = sm + buf * STAGE_WORDS;
        const uint32_t* Alo = Ahi + MAT_WORDS;
        const uint32_t* Whi = Ahi + 2 * MAT_WORDS;
        const uint32_t* Wlo = Ahi + 3 * MAT_WORDS;

#pragma unroll
        for (int ks = 0; ks < 2; ks++) {          // two k16 steps per BK=32
            const int kw = ks * 8;                // word offset of this k-step

            uint32_t ah[2][4], al[2][4];
#pragma unroll
            for (int mt = 0; mt < 2; mt++) {
                const int r0 = (m0w + mt * 16 + g) * ROWW + kw + tg;
                const int r1 = r0 + 8 * ROWW;
                ah[mt][0] = Ahi[r0];     ah[mt][1] = Ahi[r1];
                ah[mt][2] = Ahi[r0 + 4]; ah[mt][3] = Ahi[r1 + 4];
                al[mt][0] = Alo[r0];     al[mt][1] = Alo[r1];
                al[mt][2] = Alo[r0 + 4]; al[mt][3] = Alo[r1 + 4];
            }
#pragma unroll
            for (int nt = 0; nt < 8; nt++) {
                const int nr = (n0w + nt * 8 + g) * ROWW + kw + tg;
                uint32_t bh[2] = { Whi[nr], Whi[nr + 4] };
                uint32_t bl[2] = { Wlo[nr], Wlo[nr + 4] };
#pragma unroll
                for (int mt = 0; mt < 2; mt++) {
                    mma16(C[mt][nt], ah[mt], bh);
                    mma16(C[mt][nt], ah[mt], bl);
                    mma16(C[mt][nt], al[mt], bh);
                }
            }
        }
    }

    // epilogue: C + bias -> g_angle (float2 stores)
#pragma unroll
    for (int nt = 0; nt < 8; nt++) {
        const int col = bn + n0w + nt * 8 + 2 * tg;
        const float bz0 = bias[col], bz1 = bias[col + 1];
#pragma unroll
        for (int mt = 0; mt < 2; mt++) {
            const int row = bm + m0w + mt * 16 + g;
            float2 v0 = make_float2(C[mt][nt][0] + bz0, C[mt][nt][1] + bz1);
            float2 v1 = make_float2(C[mt][nt][2] + bz0, C[mt][nt][3] + bz1);
            *(float2*)(g_angle + (size_t)row * DSZ + col) = v0;
            *(float2*)(g_angle + (size_t)(row + 8) * DSZ + col) = v1;
        }
    }
}

// ---------------------------------------------------------------------------
// Complex linear scan:  g[t] = c[t]*g[t-1] + x[t]
// ---------------------------------------------------------------------------
#define EDECAY 0.999000499833375f   // expf(-0.001f)

__global__ __launch_bounds__(512) void scan_phase1(
    const float* __restrict__ x, const float* __restrict__ scale,
    const float* __restrict__ lre, const float* __restrict__ lim)
{
    const int b = blockIdx.x / NC;
    const int c = blockIdx.x % NC;
    const int d = threadIdx.x;

    const float sc = scale[d];
    const size_t base = ((size_t)b * LSZ + (size_t)c * LC) * DSZ + d;
    const float* ap = g_angle + base;
    const float* xp = x + base;

    float gr = 0.f, gi = 0.f, Pr = 1.f, Pi = 0.f;
    int tt = 0;
    if (c == 0) {
        float a0 = ap[0], x0 = xp[0];
        float s0, c0;
        __sincosf(a0 * sc, &s0, &c0);
        const float lr_ = lre[d], li_ = lim[d];
        gr = x0 + EDECAY * (c0 * lr_ - s0 * li_);
        gi = EDECAY * (c0 * li_ + s0 * lr_);
        tt = 1;
    }
    for (; tt < LC; tt++) {
        float a  = ap[(size_t)tt * DSZ];
        float xv = xp[(size_t)tt * DSZ];
        float s, co;
        __sincosf(a * sc, &s, &co);
        const float cr = EDECAY * co, ci = EDECAY * s;
        float ngr = fmaf(cr, gr, fmaf(-ci, gi, xv));
        float ngi = fmaf(cr, gi, ci * gr);
        gr = ngr; gi = ngi;
        float nPr = fmaf(cr, Pr, -ci * Pi);
        float nPi = fmaf(cr, Pi,  ci * Pr);
        Pr = nPr; Pi = nPi;
    }
    const int idx = (b * NC + c) * DSZ + d;
    g_E[idx] = make_float2(gr, gi);
    g_P[idx] = make_float2(Pr, Pi);
}

__global__ __launch_bounds__(512) void scan_phase2_ln(
    const float* __restrict__ x, const float* __restrict__ scale,
    const float* __restrict__ lre, const float* __restrict__ lim,
    const float* __restrict__ gamma, const float* __restrict__ beta,
    float* __restrict__ y)
{
    const int b = blockIdx.x / NC;
    const int c = blockIdx.x % NC;
    const int d = threadIdx.x;
    const int w = d >> 5, l = d & 31;

    __shared__ float sh_s[16], sh_ss[16];

    const float sc = scale[d];
    const float gm = gamma[d];
    const float bt = beta[d];

    float gr = 0.f, gi = 0.f;
    for (int j = 0; j < c; j++) {
        const int idx = (b * NC + j) * DSZ + d;
        const float2 P = g_P[idx];
        const float2 E = g_E[idx];
        float ngr = fmaf(P.x, gr, fmaf(-P.y, gi, E.x));
        float ngi = fmaf(P.x, gi, fmaf( P.y, gr, E.y));
        gr = ngr; gi = ngi;
    }

    const size_t base = ((size_t)b * LSZ + (size_t)c * LC) * DSZ + d;
    const float* ap = g_angle + base;
    const float* xp = x + base;
    float* yp = y + base;

    for (int tt = 0; tt < LC; tt++) {
        float a  = ap[(size_t)tt * DSZ];
        float xv = xp[(size_t)tt * DSZ];
        float s, co;
        __sincosf(a * sc, &s, &co);
        if (c == 0 && tt == 0) {
            const float lr_ = lre[d], li_ = lim[d];
            gr = xv + EDECAY * (co * lr_ - s * li_);
            gi = EDECAY * (co * li_ + s * lr_);
        } else {
            const float cr = EDECAY * co, ci = EDECAY * s;
            float ngr = fmaf(cr, gr, fmaf(-ci, gi, xv));
            float ngi = fmaf(cr, gi, ci * gr);
            gr = ngr; gi = ngi;
        }

        float sm  = gr;
        float ssq = gr * gr;
#pragma unroll
        for (int o = 16; o > 0; o >>= 1) {
            sm  += __shfl_xor_sync(0xffffffffu, sm,  o);
            ssq += __shfl_xor_sync(0xffffffffu, ssq, o);
        }
        if (l == 0) { sh_s[w] = sm; sh_ss[w] = ssq; }
        __syncthreads();
        float tot_s = 0.f, tot_ss = 0.f;
#pragma unroll
        for (int kk = 0; kk < 16; kk++) { tot_s += sh_s[kk]; tot_ss += sh_ss[kk]; }

        const float mu   = tot_s * (1.0f / DSZ);
        const float var  = tot_ss * (1.0f / DSZ) - mu * mu;
        const float rstd = rsqrtf(var + 1e-5f);
        yp[(size_t)tt * DSZ] = (gr - mu) * rstd * gm + bt;
        __syncthreads();
    }
}

// ---------------------------------------------------------------------------
// Launch
// ---------------------------------------------------------------------------
extern "C" void kernel_launch(void* const* d_in, const int* in_sizes, int n_in,
                              void* d_out, int out_size)
{
    const float* x     = (const float*)d_in[0];
    const float* fc_w  = (const float*)d_in[1];
    const float* fc_b  = (const float*)d_in[2];
    const float* scale = (const float*)d_in[3];
    const float* lre   = (const float*)d_in[4];
    const float* lim   = (const float*)d_in[5];
    const float* gamma = (const float*)d_in[6];
    const float* beta  = (const float*)d_in[7];
    float* y = (float*)d_out;

    cudaFuncSetAttribute(gemm_mma, cudaFuncAttributeMaxDynamicSharedMemorySize,
                         GEMM_SMEM);

    dim3 ggrid(DSZ / BN, MROWS / BM);   // (4, 64) = 256 CTAs
    gemm_mma<<<ggrid, 256, GEMM_SMEM>>>(x, fc_w, fc_b);

    scan_phase1<<<BSZ * NC, DSZ>>>(x, scale, lre, lim);
    scan_phase2_ln<<<BSZ * NC, DSZ>>>(x, scale, lre, lim, gamma, beta, y);
}

// round 6
// speedup vs baseline: 2.1863x; 1.3370x over previous
#include <cuda_runtime.h>
#include <cuda_fp16.h>
#include <math.h>
#include <stdint.h>

// Problem dims (fixed by the dataset)
#define BSZ 4
#define LSZ 2048
#define DSZ 512
#define MROWS (BSZ * LSZ)   // 8192

// Scan chunking
#define NC 64               // chunks along L
#define LC (LSZ / NC)       // 32 steps per chunk

// GEMM tiling
#define BM 128
#define BN 128
#define BK 32
#define NCHUNK (DSZ / BK)   // 16

// smem layout: half2 words (4B). Row = 16 data words padded to 20 (80B).
#define ROWW 20
#define ROWB 80
#define MAT_WORDS (BM * ROWW)            // 2560 words = 10KB per matrix
#define MATB (MAT_WORDS * 4)
#define STAGE_WORDS (4 * MAT_WORDS)      // Ahi|Alo|Whi|Wlo = 40KB
#define STAGEB (STAGE_WORDS * 4)
#define GEMM_SMEM (2 * STAGEB)           // double buffered: 80KB

#define SCAN_SMEM (LC * DSZ * 4)         // 64KB h tile for fused LN

// ---------------------------------------------------------------------------
// Scratch (static device globals; no runtime allocation allowed)
// ---------------------------------------------------------------------------
__device__ float  g_angle[MROWS * DSZ];
__device__ float2 g_P[BSZ * NC * DSZ];
__device__ float2 g_E[BSZ * NC * DSZ];

// ---------------------------------------------------------------------------
// helpers (baseline sm_80+ PTX only; harness compiles via compute_100)
// ---------------------------------------------------------------------------
__device__ __forceinline__ uint32_t smem_u32(const void* p) {
    uint32_t a;
    asm("{ .reg .u64 t; cvta.to.shared.u64 t, %1; cvt.u32.u64 %0, t; }" : "=r"(a) : "l"(p));
    return a;
}

__device__ __forceinline__ void split2(float x, float y, uint32_t& hi, uint32_t& lo) {
    __half2 h = __floats2half2_rn(x, y);
    float2 hf = __half22float2(h);
    __half2 l = __floats2half2_rn(x - hf.x, y - hf.y);
    hi = *reinterpret_cast<uint32_t*>(&h);
    lo = *reinterpret_cast<uint32_t*>(&l);
}

// D += A * B  (m16n8k16 fp16, fp32 accum)
__device__ __forceinline__ void mma16(float* d, const uint32_t* a,
                                      uint32_t b0, uint32_t b1) {
    asm volatile(
        "mma.sync.aligned.m16n8k16.row.col.f32.f16.f16.f32 "
        "{%0,%1,%2,%3}, {%4,%5,%6,%7}, {%8,%9}, {%0,%1,%2,%3};"
        : "+f"(d[0]), "+f"(d[1]), "+f"(d[2]), "+f"(d[3])
        : "r"(a[0]), "r"(a[1]), "r"(a[2]), "r"(a[3]), "r"(b0), "r"(b1));
}

__device__ __forceinline__ void ldm4(uint32_t* r, uint32_t addr) {
    asm volatile("ldmatrix.sync.aligned.m8n8.x4.shared.b16 {%0,%1,%2,%3}, [%4];"
        : "=r"(r[0]), "=r"(r[1]), "=r"(r[2]), "=r"(r[3]) : "r"(addr));
}

// ---------------------------------------------------------------------------
// GEMM: angle = x @ W^T + b, split-fp16 (hi*hi + hi*lo + lo*hi), mma.sync.
// 256 threads = 8 warps (4m x 2n), warp tile 32x64. ldmatrix fragment loads.
// ---------------------------------------------------------------------------
__global__ __launch_bounds__(256, 1) void gemm_mma(
    const float* __restrict__ A, const float* __restrict__ W,
    const float* __restrict__ bias)
{
    extern __shared__ char dynsm[];
    uint32_t* sm = (uint32_t*)dynsm;
    const uint32_t sb = smem_u32(dynsm);

    const int tid  = threadIdx.x;
    const int wid  = tid >> 5;
    const int lane = tid & 31;
    const int g    = lane >> 2;
    const int tg   = lane & 3;
    const int bm   = blockIdx.y * BM;
    const int bn   = blockIdx.x * BN;
    const int m0w  = (wid >> 1) * 32;
    const int n0w  = (wid & 1) * 64;

    // ldmatrix addressing: lane -> (row = lane&15, k-half = lane>>4)
    const int lmr = lane & 15;
    const int lmk = (lane >> 4) * 16;   // bytes
    uint32_t aHi[2], bHi[4];
#pragma unroll
    for (int mt = 0; mt < 2; mt++)
        aHi[mt] = sb + (m0w + mt * 16 + lmr) * ROWB + lmk;
#pragma unroll
    for (int p = 0; p < 4; p++)
        bHi[p] = sb + 2 * MATB + (n0w + p * 16 + lmr) * ROWB + lmk;

    // staging: row = tid>>1 (0..127), 16-float half = tid&1
    const int srow = tid >> 1;
    const int h16  = tid & 1;
    const float* Ag = A + (size_t)(bm + srow) * DSZ + h16 * 16;
    const float* Wg = W + (size_t)(bn + srow) * DSZ + h16 * 16;

    float4 pa[4], pw[4];
    auto ldg_chunk = [&](int c) {
        const float* ap = Ag + c * BK;
        const float* wp = Wg + c * BK;
#pragma unroll
        for (int j = 0; j < 4; j++) {
            pa[j] = *(const float4*)(ap + 4 * j);
            pw[j] = *(const float4*)(wp + 4 * j);
        }
    };
    auto sts_chunk = [&](int buf) {
        uint32_t* st = sm + buf * STAGE_WORDS;
        const int base = srow * ROWW + h16 * 8;
        uint4 H0, H1, L0, L1;
        split2(pa[0].x, pa[0].y, H0.x, L0.x);
        split2(pa[0].z, pa[0].w, H0.y, L0.y);
        split2(pa[1].x, pa[1].y, H0.z, L0.z);
        split2(pa[1].z, pa[1].w, H0.w, L0.w);
        split2(pa[2].x, pa[2].y, H1.x, L1.x);
        split2(pa[2].z, pa[2].w, H1.y, L1.y);
        split2(pa[3].x, pa[3].y, H1.z, L1.z);
        split2(pa[3].z, pa[3].w, H1.w, L1.w);
        *(uint4*)(st + base)                 = H0;
        *(uint4*)(st + base + 4)             = H1;
        *(uint4*)(st + MAT_WORDS + base)     = L0;
        *(uint4*)(st + MAT_WORDS + base + 4) = L1;
        split2(pw[0].x, pw[0].y, H0.x, L0.x);
        split2(pw[0].z, pw[0].w, H0.y, L0.y);
        split2(pw[1].x, pw[1].y, H0.z, L0.z);
        split2(pw[1].z, pw[1].w, H0.w, L0.w);
        split2(pw[2].x, pw[2].y, H1.x, L1.x);
        split2(pw[2].z, pw[2].w, H1.y, L1.y);
        split2(pw[3].x, pw[3].y, H1.z, L1.z);
        split2(pw[3].z, pw[3].w, H1.w, L1.w);
        *(uint4*)(st + 2 * MAT_WORDS + base)     = H0;
        *(uint4*)(st + 2 * MAT_WORDS + base + 4) = H1;
        *(uint4*)(st + 3 * MAT_WORDS + base)     = L0;
        *(uint4*)(st + 3 * MAT_WORDS + base + 4) = L1;
    };

    float C[2][8][4];
#pragma unroll
    for (int mt = 0; mt < 2; mt++)
#pragma unroll
        for (int nt = 0; nt < 8; nt++)
#pragma unroll
            for (int j = 0; j < 4; j++) C[mt][nt][j] = 0.f;

    ldg_chunk(0);
    for (int c = 0; c < NCHUNK; c++) {
        const int buf = c & 1;
        sts_chunk(buf);
        __syncthreads();
        if (c + 1 < NCHUNK) ldg_chunk(c + 1);

        const uint32_t boff = buf * STAGEB;
#pragma unroll
        for (int ks = 0; ks < 2; ks++) {
            const uint32_t off = boff + ks * 32;   // k16 step = 32 bytes
            uint32_t ah[2][4], al[2][4];
#pragma unroll
            for (int mt = 0; mt < 2; mt++) {
                ldm4(ah[mt], aHi[mt] + off);
                ldm4(al[mt], aHi[mt] + MATB + off);
            }
#pragma unroll
            for (int p = 0; p < 4; p++) {
                uint32_t bh[4], bl[4];
                ldm4(bh, bHi[p] + off);
                ldm4(bl, bHi[p] + MATB + off);
#pragma unroll
                for (int mt = 0; mt < 2; mt++) {
                    mma16(C[mt][2 * p],     ah[mt], bh[0], bh[2]);
                    mma16(C[mt][2 * p],     ah[mt], bl[0], bl[2]);
                    mma16(C[mt][2 * p],     al[mt], bh[0], bh[2]);
                    mma16(C[mt][2 * p + 1], ah[mt], bh[1], bh[3]);
                    mma16(C[mt][2 * p + 1], ah[mt], bl[1], bl[3]);
                    mma16(C[mt][2 * p + 1], al[mt], bh[1], bh[3]);
                }
            }
        }
    }

    // epilogue: C + bias -> g_angle (float2 stores)
#pragma unroll
    for (int nt = 0; nt < 8; nt++) {
        const int col = bn + n0w + nt * 8 + 2 * tg;
        const float bz0 = bias[col], bz1 = bias[col + 1];
#pragma unroll
        for (int mt = 0; mt < 2; mt++) {
            const int row = bm + m0w + mt * 16 + g;
            float2 v0 = make_float2(C[mt][nt][0] + bz0, C[mt][nt][1] + bz1);
            float2 v1 = make_float2(C[mt][nt][2] + bz0, C[mt][nt][3] + bz1);
            *(float2*)(g_angle + (size_t)row * DSZ + col) = v0;
            *(float2*)(g_angle + (size_t)(row + 8) * DSZ + col) = v1;
        }
    }
}

// ---------------------------------------------------------------------------
// Complex linear scan:  g[t] = c[t]*g[t-1] + x[t]
// ---------------------------------------------------------------------------
#define EDECAY 0.999000499833375f   // expf(-0.001f)

__global__ __launch_bounds__(512) void scan_phase1(
    const float* __restrict__ x, const float* __restrict__ scale,
    const float* __restrict__ lre, const float* __restrict__ lim)
{
    const int b = blockIdx.x / NC;
    const int c = blockIdx.x % NC;
    const int d = threadIdx.x;

    const float sc = scale[d];
    const size_t base = ((size_t)b * LSZ + (size_t)c * LC) * DSZ + d;
    const float* ap = g_angle + base;
    const float* xp = x + base;

    float gr = 0.f, gi = 0.f, Pr = 1.f, Pi = 0.f;
    int tt = 0;
    if (c == 0) {
        float a0 = ap[0], x0 = xp[0];
        float s0, c0;
        __sincosf(a0 * sc, &s0, &c0);
        const float lr_ = lre[d], li_ = lim[d];
        gr = x0 + EDECAY * (c0 * lr_ - s0 * li_);
        gi = EDECAY * (c0 * li_ + s0 * lr_);
        tt = 1;
    }
    for (; tt < LC; tt++) {
        float a  = ap[(size_t)tt * DSZ];
        float xv = xp[(size_t)tt * DSZ];
        float s, co;
        __sincosf(a * sc, &s, &co);
        const float cr = EDECAY * co, ci = EDECAY * s;
        float ngr = fmaf(cr, gr, fmaf(-ci, gi, xv));
        float ngi = fmaf(cr, gi, ci * gr);
        gr = ngr; gi = ngi;
        float nPr = fmaf(cr, Pr, -ci * Pi);
        float nPi = fmaf(cr, Pi,  ci * Pr);
        Pr = nPr; Pi = nPi;
    }
    const int idx = (b * NC + c) * DSZ + d;
    g_E[idx] = make_float2(gr, gi);
    g_P[idx] = make_float2(Pr, Pi);
}

// Phase 2: barrier-free scan into smem h[LC][DSZ], then per-warp LN rows.
__global__ __launch_bounds__(512) void scan_phase2_ln(
    const float* __restrict__ x, const float* __restrict__ scale,
    const float* __restrict__ lre, const float* __restrict__ lim,
    const float* __restrict__ gamma, const float* __restrict__ beta,
    float* __restrict__ y)
{
    extern __shared__ char dynsm[];
    float* hsm = (float*)dynsm;   // [LC][DSZ]

    const int b = blockIdx.x / NC;
    const int c = blockIdx.x % NC;
    const int d = threadIdx.x;
    const int lane = d & 31, w = d >> 5;

    const float sc = scale[d];

    // fold carries from preceding chunks
    float gr = 0.f, gi = 0.f;
    for (int j = 0; j < c; j++) {
        const int idx = (b * NC + j) * DSZ + d;
        const float2 P = g_P[idx];
        const float2 E = g_E[idx];
        float ngr = fmaf(P.x, gr, fmaf(-P.y, gi, E.x));
        float ngi = fmaf(P.x, gi, fmaf( P.y, gr, E.y));
        gr = ngr; gi = ngi;
    }

    const size_t base = ((size_t)b * LSZ + (size_t)c * LC) * DSZ + d;
    const float* ap = g_angle + base;
    const float* xp = x + base;

    int tt = 0;
    if (c == 0) {
        float a0 = ap[0], x0 = xp[0];
        float s0, c0;
        __sincosf(a0 * sc, &s0, &c0);
        const float lr_ = lre[d], li_ = lim[d];
        gr = x0 + EDECAY * (c0 * lr_ - s0 * li_);
        gi = EDECAY * (c0 * li_ + s0 * lr_);
        hsm[d] = gr;
        tt = 1;
    }
    for (; tt < LC; tt++) {
        float a  = ap[(size_t)tt * DSZ];
        float xv = xp[(size_t)tt * DSZ];
        float s, co;
        __sincosf(a * sc, &s, &co);
        const float cr = EDECAY * co, ci = EDECAY * s;
        float ngr = fmaf(cr, gr, fmaf(-ci, gi, xv));
        float ngi = fmaf(cr, gi, ci * gr);
        gr = ngr; gi = ngi;
        hsm[tt * DSZ + d] = gr;
    }
    __syncthreads();

    // LN: warp w handles rows w and w+16; each lane owns 4 float4 slots.
    float4 g4[4], b4[4];
#pragma unroll
    for (int j = 0; j < 4; j++) {
        g4[j] = ((const float4*)gamma)[lane + j * 32];
        b4[j] = ((const float4*)beta)[lane + j * 32];
    }
    float* yrowbase = y + ((size_t)b * LSZ + (size_t)c * LC) * DSZ;

#pragma unroll
    for (int rr = w; rr < LC; rr += 16) {
        const float4* hp = (const float4*)(hsm + rr * DSZ);
        float4 v[4];
        float s = 0.f, ss = 0.f;
#pragma unroll
        for (int j = 0; j < 4; j++) {
            v[j] = hp[lane + j * 32];
            s  += v[j].x + v[j].y + v[j].z + v[j].w;
            ss += v[j].x * v[j].x + v[j].y * v[j].y
                + v[j].z * v[j].z + v[j].w * v[j].w;
        }
#pragma unroll
        for (int o = 16; o > 0; o >>= 1) {
            s  += __shfl_xor_sync(0xffffffffu, s,  o);
            ss += __shfl_xor_sync(0xffffffffu, ss, o);
        }
        const float mu   = s * (1.0f / DSZ);
        const float var  = ss * (1.0f / DSZ) - mu * mu;
        const float rstd = rsqrtf(var + 1e-5f);

        float4* yp = (float4*)(yrowbase + (size_t)rr * DSZ);
#pragma unroll
        for (int j = 0; j < 4; j++) {
            float4 o;
            o.x = (v[j].x - mu) * rstd * g4[j].x + b4[j].x;
            o.y = (v[j].y - mu) * rstd * g4[j].y + b4[j].y;
            o.z = (v[j].z - mu) * rstd * g4[j].z + b4[j].z;
            o.w = (v[j].w - mu) * rstd * g4[j].w + b4[j].w;
            yp[lane + j * 32] = o;
        }
    }
}

// ---------------------------------------------------------------------------
// Launch
// ---------------------------------------------------------------------------
extern "C" void kernel_launch(void* const* d_in, const int* in_sizes, int n_in,
                              void* d_out, int out_size)
{
    const float* x     = (const float*)d_in[0];
    const float* fc_w  = (const float*)d_in[1];
    const float* fc_b  = (const float*)d_in[2];
    const float* scale = (const float*)d_in[3];
    const float* lre   = (const float*)d_in[4];
    const float* lim   = (const float*)d_in[5];
    const float* gamma = (const float*)d_in[6];
    const float* beta  = (const float*)d_in[7];
    float* y = (float*)d_out;

    cudaFuncSetAttribute(gemm_mma, cudaFuncAttributeMaxDynamicSharedMemorySize,
                         GEMM_SMEM);
    cudaFuncSetAttribute(scan_phase2_ln, cudaFuncAttributeMaxDynamicSharedMemorySize,
                         SCAN_SMEM);

    dim3 ggrid(DSZ / BN, MROWS / BM);   // (4, 64) = 256 CTAs
    gemm_mma<<<ggrid, 256, GEMM_SMEM>>>(x, fc_w, fc_b);

    scan_phase1<<<BSZ * NC, DSZ>>>(x, scale, lre, lim);
    scan_phase2_ln<<<BSZ * NC, DSZ, SCAN_SMEM>>>(x, scale, lre, lim, gamma, beta, y);
}